// round 8
// baseline (speedup 1.0000x reference)
#include <cuda_runtime.h>

#define N_NODES 50000
#define N_EDGES 800000
#define NEG_SLOPE 0.2f

// ---------------- scratch (device globals) ---------------------------------
__device__ __align__(16) float g_xh[(size_t)N_NODES * 128]; // x @ W
__device__ __align__(16) float g_si[N_NODES * 4];           // <xh, a_i> per head
__device__ __align__(16) float g_sj[N_NODES * 4];           // <xh, a_j> per head
__device__ float g_sew[32];                                 // folded We * a_e  [c][h]
__device__ int   g_cur[N_NODES];                            // counts -> cursors
__device__ int   g_off[N_NODES + 1];                        // CSR offsets by dst
__device__ int   g_ssrc[N_EDGES];                           // dst-sorted src ids
__device__ __align__(16) float g_salpha[(size_t)N_EDGES * 4]; // dst-sorted logits

// ---------------- K0: init counts, fold We*a_e ------------------------------
__global__ void k_init(const float* __restrict__ We, const float* __restrict__ att) {
    int i = blockIdx.x * blockDim.x + threadIdx.x;
    if (i < N_NODES) g_cur[i] = 0;
    if (i == 0) g_off[N_NODES] = N_EDGES;
    if (i < 32) {
        int h = i & 3, c = i >> 2;
        float s = 0.0f;
        #pragma unroll
        for (int p = 0; p < 4; p++)
            s += __ldg(We + c * 16 + h * 4 + p) * __ldg(att + h * 68 + 64 + p);
        g_sew[c * 4 + h] = s;
    }
}

// ---------------- K1: histogram of dst --------------------------------------
__global__ void k_hist(const int* __restrict__ ei) {
    int e = blockIdx.x * blockDim.x + threadIdx.x;
    if (e < N_EDGES) atomicAdd(&g_cur[__ldg(ei + N_EDGES + e)], 1);
}

// ---------------- K2: exclusive scan (single block, 1024 threads) ----------
__global__ __launch_bounds__(1024) void k_scan() {
    __shared__ int part[1024];
    const int PER = (N_NODES + 1023) / 1024;  // 49
    int t = threadIdx.x;
    int base = t * PER;
    int s = 0;
    for (int i = 0; i < PER; i++) {
        int idx = base + i;
        if (idx < N_NODES) s += g_cur[idx];
    }
    part[t] = s;
    __syncthreads();
    for (int off = 1; off < 1024; off <<= 1) {
        int v = (t >= off) ? part[t - off] : 0;
        __syncthreads();
        part[t] += v;
        __syncthreads();
    }
    int run = part[t] - s;
    for (int i = 0; i < PER; i++) {
        int idx = base + i;
        if (idx < N_NODES) {
            int c = g_cur[idx];
            g_off[idx] = run;
            g_cur[idx] = run;
            run += c;
        }
    }
}

// ---------------- K3: register-tiled GEMM xh = x @ W (+ s_i, s_j) ----------
// 128-row x 128-col tile per block, 256 threads, 2 rows x 32 cols per thread.
// Phases of 32 k; x staged TRANSPOSED in smem (pad 129 -> conflict-free).
#define KP 32
__global__ __launch_bounds__(256) void k_gemm(const float* __restrict__ x,
                                              const float* __restrict__ W,
                                              const float* __restrict__ att) {
    __shared__ __align__(16) float sW[KP][128];
    __shared__ float sX[KP][129];
    int t = threadIdx.x;
    int rp = t & 63;      // row-pair index: rows rp, rp+64
    int cg = t >> 6;      // head / col group 0..3
    int blockRow = blockIdx.x * 128;

    float acc0[32], acc1[32];
    #pragma unroll
    for (int i = 0; i < 32; i++) { acc0[i] = 0.0f; acc1[i] = 0.0f; }

    #pragma unroll
    for (int phase = 0; phase < 4; phase++) {
        int k0 = phase * KP;
        __syncthreads();
        // stage W[k0..k0+31][0..127]: 1024 float4, 4 per thread
        #pragma unroll
        for (int i = 0; i < 4; i++) {
            int idx = i * 256 + t;
            int k = idx >> 5, c4 = idx & 31;
            *(float4*)&sW[k][c4 * 4] =
                __ldg((const float4*)(W + (size_t)(k0 + k) * 128) + c4);
        }
        // stage x transposed: sX[k][row]
        #pragma unroll
        for (int i = 0; i < 4; i++) {
            int idx = i * 256 + t;
            int row = idx >> 3, k4 = idx & 7;
            int gr = blockRow + row;
            if (gr >= N_NODES) gr = N_NODES - 1;
            float4 v = __ldg((const float4*)(x + (size_t)gr * 128 + k0) + k4);
            sX[k4 * 4 + 0][row] = v.x;
            sX[k4 * 4 + 1][row] = v.y;
            sX[k4 * 4 + 2][row] = v.z;
            sX[k4 * 4 + 3][row] = v.w;
        }
        __syncthreads();

        #pragma unroll
        for (int k = 0; k < KP; k++) {
            float xa = sX[k][rp];
            float xb = sX[k][rp + 64];
            const float4* wr = (const float4*)&sW[k][cg * 32];
            #pragma unroll
            for (int j = 0; j < 8; j++) {
                float4 w = wr[j];
                acc0[j*4+0] += xa * w.x; acc0[j*4+1] += xa * w.y;
                acc0[j*4+2] += xa * w.z; acc0[j*4+3] += xa * w.w;
                acc1[j*4+0] += xb * w.x; acc1[j*4+1] += xb * w.y;
                acc1[j*4+2] += xb * w.z; acc1[j*4+3] += xb * w.w;
            }
        }
    }

    const float* ap = att + cg * 68;
    #pragma unroll
    for (int rsel = 0; rsel < 2; rsel++) {
        int grow = blockRow + rp + rsel * 64;
        if (grow >= N_NODES) continue;
        float* acc = rsel ? acc1 : acc0;
        float4* op = (float4*)(g_xh + (size_t)grow * 128 + cg * 32);
        float si = 0.0f, sj = 0.0f;
        #pragma unroll
        for (int j = 0; j < 8; j++) {
            op[j] = make_float4(acc[j*4+0], acc[j*4+1], acc[j*4+2], acc[j*4+3]);
            #pragma unroll
            for (int cc = 0; cc < 4; cc++) {
                int o = j * 4 + cc;
                si += acc[o] * __ldg(ap + o);
                sj += acc[o] * __ldg(ap + 32 + o);
            }
        }
        g_si[grow * 4 + cg] = si;
        g_sj[grow * 4 + cg] = sj;
    }
}

// ---------------- K4: edge logits + scatter into CSR (no segment max) ------
__global__ void k_edge(const int* __restrict__ ei, const float* __restrict__ eattr) {
    int e = blockIdx.x * blockDim.x + threadIdx.x;
    if (e >= N_EDGES) return;
    int src = __ldg(ei + e);
    int dst = __ldg(ei + N_EDGES + e);
    float4 f0 = __ldg((const float4*)eattr + (size_t)e * 2);
    float4 f1 = __ldg((const float4*)eattr + (size_t)e * 2 + 1);
    float f[8] = {f0.x, f0.y, f0.z, f0.w, f1.x, f1.y, f1.z, f1.w};
    float4 si = *(const float4*)(g_si + dst * 4);
    float4 sj = *(const float4*)(g_sj + src * 4);
    float sih[4] = {si.x, si.y, si.z, si.w};
    float sjh[4] = {sj.x, sj.y, sj.z, sj.w};
    float a[4];
    #pragma unroll
    for (int h = 0; h < 4; h++) {
        float se = 0.0f;
        #pragma unroll
        for (int c = 0; c < 8; c++) se += f[c] * g_sew[c * 4 + h];
        float v = sih[h] + sjh[h] + se;
        a[h] = v > 0.0f ? v : NEG_SLOPE * v;
    }
    int pos = atomicAdd(&g_cur[dst], 1);
    g_ssrc[pos] = src;
    *((float4*)g_salpha + pos) = make_float4(a[0], a[1], a[2], a[3]);
}

// ---------------- K5: warp-per-node aggregation (fused softmax, no max) ----
__global__ __launch_bounds__(256) void k_aggr(const float* __restrict__ bias,
                                              float* __restrict__ out) {
    int w = (blockIdx.x * blockDim.x + threadIdx.x) >> 5;
    if (w >= N_NODES) return;
    int lane = threadIdx.x & 31;
    int h = lane >> 3;

    int start = g_off[w];
    int end   = g_off[w + 1];

    float ax = 0.0f, ay = 0.0f, az = 0.0f, aw = 0.0f, den = 0.0f;

    #pragma unroll 4
    for (int e = start; e < end; e++) {
        int src = __ldg(&g_ssrc[e]);
        float a = __ldg(&g_salpha[(size_t)e * 4 + h]);
        float ea = __expf(a);
        den += ea;
        float4 xv = __ldg((const float4*)(g_xh + (size_t)src * 128) + lane);
        ax += ea * xv.x; ay += ea * xv.y; az += ea * xv.z; aw += ea * xv.w;
    }

    float inv = 1.0f / (den + 1e-16f);
    float4 b = __ldg((const float4*)bias + lane);
    ((float4*)out)[(size_t)w * 32 + lane] =
        make_float4(ax * inv + b.x, ay * inv + b.y, az * inv + b.z, aw * inv + b.w);
}

// ---------------- launch ----------------------------------------------------
extern "C" void kernel_launch(void* const* d_in, const int* in_sizes, int n_in,
                              void* d_out, int out_size) {
    const float* x     = (const float*)d_in[0];
    const int*   ei    = (const int*)  d_in[1];
    const float* eattr = (const float*)d_in[2];
    const float* W     = (const float*)d_in[3];
    const float* We    = (const float*)d_in[4];
    const float* att   = (const float*)d_in[5];
    const float* bias  = (const float*)d_in[6];
    float* out = (float*)d_out;

    k_init <<<(N_NODES + 255) / 256, 256>>>(We, att);
    k_hist <<<(N_EDGES + 255) / 256, 256>>>(ei);
    k_scan <<<1, 1024>>>();
    k_gemm <<<(N_NODES + 127) / 128, 256>>>(x, W, att);
    k_edge <<<(N_EDGES + 255) / 256, 256>>>(ei, eattr);
    k_aggr <<<((size_t)N_NODES * 32 + 255) / 256, 256>>>(bias, out);
}

// round 9
// speedup vs baseline: 1.2148x; 1.2148x over previous
#include <cuda_runtime.h>

#define N_NODES 50000
#define N_EDGES 800000
#define NEG_SLOPE 0.2f

// ---------------- scratch (device globals) ---------------------------------
__device__ __align__(16) float g_xh[(size_t)N_NODES * 128]; // x @ W
__device__ __align__(16) float g_si[N_NODES * 4];           // <xh, a_i> per head
__device__ __align__(16) float g_sj[N_NODES * 4];           // <xh, a_j> per head
__device__ float g_sew[32];                                 // folded We * a_e  [c][h]
__device__ int   g_cur[N_NODES];                            // counts -> cursors
__device__ int   g_off[N_NODES + 1];                        // CSR offsets by dst
__device__ int   g_ssrc[N_EDGES];                           // dst-sorted src ids
__device__ __align__(16) float g_salpha[(size_t)N_EDGES * 4]; // dst-sorted exp(logit)

// ---------------- K0: init counts, fold We*a_e ------------------------------
__global__ void k_init(const float* __restrict__ We, const float* __restrict__ att) {
    int i = blockIdx.x * blockDim.x + threadIdx.x;
    if (i < N_NODES) g_cur[i] = 0;
    if (i == 0) g_off[N_NODES] = N_EDGES;
    if (i < 32) {
        int h = i & 3, c = i >> 2;
        float s = 0.0f;
        #pragma unroll
        for (int p = 0; p < 4; p++)
            s += __ldg(We + c * 16 + h * 4 + p) * __ldg(att + h * 68 + 64 + p);
        g_sew[c * 4 + h] = s;
    }
}

// ---------------- K1: histogram of dst --------------------------------------
__global__ void k_hist(const int* __restrict__ ei) {
    int e = blockIdx.x * blockDim.x + threadIdx.x;
    if (e < N_EDGES) atomicAdd(&g_cur[__ldg(ei + N_EDGES + e)], 1);
}

// ---------------- K2: exclusive scan (single block, 1024 threads) ----------
__global__ __launch_bounds__(1024) void k_scan() {
    __shared__ int part[1024];
    const int PER = (N_NODES + 1023) / 1024;
    int t = threadIdx.x;
    int base = t * PER;
    int s = 0;
    for (int i = 0; i < PER; i++) {
        int idx = base + i;
        if (idx < N_NODES) s += g_cur[idx];
    }
    part[t] = s;
    __syncthreads();
    for (int off = 1; off < 1024; off <<= 1) {
        int v = (t >= off) ? part[t - off] : 0;
        __syncthreads();
        part[t] += v;
        __syncthreads();
    }
    int run = part[t] - s;
    for (int i = 0; i < PER; i++) {
        int idx = base + i;
        if (idx < N_NODES) {
            int c = g_cur[idx];
            g_off[idx] = run;
            g_cur[idx] = run;
            run += c;
        }
    }
}

// ---------------- K3: GEMM xh = x @ W ---------------------------------------
// Block: 256 threads, tile 64 rows x 128 cols. Thread: 8 rows x 4 cols.
// Per k: 2 LDS.128 (x, transposed in smem) + 1 LDS.128 (W) per 32 FFMA.
#define KP 32
#define XSTR 68
__global__ __launch_bounds__(256) void k_gemm(const float* __restrict__ x,
                                              const float* __restrict__ W) {
    __shared__ __align__(16) float sW[KP][128];
    __shared__ __align__(16) float sX[KP][XSTR];
    int t = threadIdx.x;
    int r8 = (t & 7) * 8;   // rows r8..r8+7 of the 64-row tile
    int c4 = t >> 3;        // cols c4*4..c4*4+3
    int blockRow = blockIdx.x * 64;

    float acc[8][4];
    #pragma unroll
    for (int r = 0; r < 8; r++)
        #pragma unroll
        for (int c = 0; c < 4; c++) acc[r][c] = 0.0f;

    #pragma unroll
    for (int phase = 0; phase < 4; phase++) {
        int k0 = phase * KP;
        __syncthreads();
        // stage W[k0..k0+31][0..127]: 1024 float4, 4 per thread
        #pragma unroll
        for (int i = 0; i < 4; i++) {
            int idx = i * 256 + t;
            int k = idx >> 5, cc = idx & 31;
            *(float4*)&sW[k][cc * 4] =
                __ldg((const float4*)(W + (size_t)(k0 + k) * 128) + cc);
        }
        // stage x transposed: sX[k][row], 512 float4, 2 per thread
        #pragma unroll
        for (int i = 0; i < 2; i++) {
            int idx = i * 256 + t;
            int row = idx >> 3, k4 = idx & 7;
            int gr = blockRow + row;
            if (gr >= N_NODES) gr = N_NODES - 1;
            float4 v = __ldg((const float4*)(x + (size_t)gr * 128 + k0) + k4);
            sX[k4 * 4 + 0][row] = v.x;
            sX[k4 * 4 + 1][row] = v.y;
            sX[k4 * 4 + 2][row] = v.z;
            sX[k4 * 4 + 3][row] = v.w;
        }
        __syncthreads();

        #pragma unroll
        for (int k = 0; k < KP; k++) {
            float4 x0 = *(const float4*)&sX[k][r8];
            float4 x1 = *(const float4*)&sX[k][r8 + 4];
            float4 w  = *(const float4*)&sW[k][c4 * 4];
            float xr[8] = {x0.x, x0.y, x0.z, x0.w, x1.x, x1.y, x1.z, x1.w};
            #pragma unroll
            for (int r = 0; r < 8; r++) {
                acc[r][0] += xr[r] * w.x;
                acc[r][1] += xr[r] * w.y;
                acc[r][2] += xr[r] * w.z;
                acc[r][3] += xr[r] * w.w;
            }
        }
    }

    #pragma unroll
    for (int r = 0; r < 8; r++) {
        int grow = blockRow + r8 + r;
        if (grow < N_NODES)
            *(float4*)(g_xh + (size_t)grow * 128 + c4 * 4) =
                make_float4(acc[r][0], acc[r][1], acc[r][2], acc[r][3]);
    }
}

// ---------------- K3b: s_i, s_j = <xh[n,h,:], a_i/a_j> ----------------------
__global__ void k_sisj(const float* __restrict__ att) {
    int i = blockIdx.x * blockDim.x + threadIdx.x;  // node*4 + head
    if (i >= N_NODES * 4) return;
    int node = i >> 2, h = i & 3;
    const float4* xp = (const float4*)(g_xh + (size_t)node * 128 + h * 32);
    const float4* ai = (const float4*)(att + h * 68);
    const float4* aj = (const float4*)(att + h * 68 + 32);
    float si = 0.0f, sj = 0.0f;
    #pragma unroll
    for (int j = 0; j < 8; j++) {
        float4 v = __ldg(xp + j);
        float4 a = __ldg(ai + j);
        float4 b = __ldg(aj + j);
        si += v.x * a.x + v.y * a.y + v.z * a.z + v.w * a.w;
        sj += v.x * b.x + v.y * b.y + v.z * b.z + v.w * b.w;
    }
    g_si[i] = si;
    g_sj[i] = sj;
}

// ---------------- K4: edge logits -> exp, scatter into CSR ------------------
__global__ void k_edge(const int* __restrict__ ei, const float* __restrict__ eattr) {
    int e = blockIdx.x * blockDim.x + threadIdx.x;
    if (e >= N_EDGES) return;
    int src = __ldg(ei + e);
    int dst = __ldg(ei + N_EDGES + e);
    float4 f0 = __ldg((const float4*)eattr + (size_t)e * 2);
    float4 f1 = __ldg((const float4*)eattr + (size_t)e * 2 + 1);
    float f[8] = {f0.x, f0.y, f0.z, f0.w, f1.x, f1.y, f1.z, f1.w};
    float4 si = *(const float4*)(g_si + dst * 4);
    float4 sj = *(const float4*)(g_sj + src * 4);
    float sih[4] = {si.x, si.y, si.z, si.w};
    float sjh[4] = {sj.x, sj.y, sj.z, sj.w};
    float a[4];
    #pragma unroll
    for (int h = 0; h < 4; h++) {
        float se = 0.0f;
        #pragma unroll
        for (int c = 0; c < 8; c++) se += f[c] * g_sew[c * 4 + h];
        float v = sih[h] + sjh[h] + se;
        v = v > 0.0f ? v : NEG_SLOPE * v;
        a[h] = __expf(v);   // store exp directly (no segment-max needed; |v| small)
    }
    int pos = atomicAdd(&g_cur[dst], 1);
    g_ssrc[pos] = src;
    *((float4*)g_salpha + pos) = make_float4(a[0], a[1], a[2], a[3]);
}

// ---------------- K5: warp-per-node aggregation ------------------------------
__global__ __launch_bounds__(256) void k_aggr(const float* __restrict__ bias,
                                              float* __restrict__ out) {
    int w = (blockIdx.x * blockDim.x + threadIdx.x) >> 5;
    if (w >= N_NODES) return;
    int lane = threadIdx.x & 31;
    int h = lane >> 3;

    int start = g_off[w];
    int end   = g_off[w + 1];

    float ax = 0.0f, ay = 0.0f, az = 0.0f, aw = 0.0f, den = 0.0f;

    #pragma unroll 4
    for (int e = start; e < end; e++) {
        int src = __ldg(&g_ssrc[e]);
        float ea = __ldg(&g_salpha[(size_t)e * 4 + h]);
        den += ea;
        float4 xv = __ldg((const float4*)(g_xh + (size_t)src * 128) + lane);
        ax += ea * xv.x; ay += ea * xv.y; az += ea * xv.z; aw += ea * xv.w;
    }

    float inv = 1.0f / (den + 1e-16f);
    float4 b = __ldg((const float4*)bias + lane);
    ((float4*)out)[(size_t)w * 32 + lane] =
        make_float4(ax * inv + b.x, ay * inv + b.y, az * inv + b.z, aw * inv + b.w);
}

// ---------------- launch ----------------------------------------------------
extern "C" void kernel_launch(void* const* d_in, const int* in_sizes, int n_in,
                              void* d_out, int out_size) {
    const float* x     = (const float*)d_in[0];
    const int*   ei    = (const int*)  d_in[1];
    const float* eattr = (const float*)d_in[2];
    const float* W     = (const float*)d_in[3];
    const float* We    = (const float*)d_in[4];
    const float* att   = (const float*)d_in[5];
    const float* bias  = (const float*)d_in[6];
    float* out = (float*)d_out;

    k_init <<<(N_NODES + 255) / 256, 256>>>(We, att);
    k_hist <<<(N_EDGES + 255) / 256, 256>>>(ei);
    k_scan <<<1, 1024>>>();
    k_gemm <<<(N_NODES + 63) / 64, 256>>>(x, W);
    k_sisj <<<(N_NODES * 4 + 255) / 256, 256>>>(att);
    k_edge <<<(N_EDGES + 255) / 256, 256>>>(ei, eattr);
    k_aggr <<<((size_t)N_NODES * 32 + 255) / 256, 256>>>(bias, out);
}

// round 10
// speedup vs baseline: 1.3635x; 1.1224x over previous
#include <cuda_runtime.h>

#define N_NODES 50000
#define N_EDGES 800000
#define NEG_SLOPE 0.2f

// ---------------- scratch (device globals) ---------------------------------
__device__ __align__(16) float g_xh[(size_t)N_NODES * 128]; // x @ W
__device__ __align__(16) float g_si[N_NODES * 4];           // <xh, a_i> per head
__device__ __align__(16) float g_sj[N_NODES * 4];           // <xh, a_j> per head
__device__ float g_sew[32];                                 // folded We * a_e  [c][h]
__device__ int   g_cur[N_NODES];                            // counts -> cursors
__device__ int   g_off[N_NODES + 1];                        // CSR offsets by dst
__device__ int   g_ssrc[N_EDGES];                           // dst-sorted src ids
__device__ __align__(16) float g_salpha[(size_t)N_EDGES * 4]; // dst-sorted exp(logit)

// ---------------- f32x2 packed-FMA helpers (Blackwell FFMA2) ----------------
__device__ __forceinline__ void ffma2(unsigned long long& d,
                                      unsigned long long a,
                                      unsigned long long b) {
    asm("fma.rn.f32x2 %0, %1, %2, %0;" : "+l"(d) : "l"(a), "l"(b));
}
__device__ __forceinline__ unsigned long long bcast2(float x) {
    unsigned long long r;
    unsigned int u = __float_as_uint(x);
    asm("mov.b64 %0, {%1, %1};" : "=l"(r) : "r"(u));
    return r;
}
__device__ __forceinline__ unsigned long long pack2(float lo, float hi) {
    unsigned long long r;
    unsigned int a = __float_as_uint(lo), b = __float_as_uint(hi);
    asm("mov.b64 %0, {%1, %2};" : "=l"(r) : "r"(a), "r"(b));
    return r;
}
__device__ __forceinline__ float2 unpack2(unsigned long long v) {
    unsigned int a, b;
    asm("mov.b64 {%0, %1}, %2;" : "=r"(a), "=r"(b) : "l"(v));
    return make_float2(__uint_as_float(a), __uint_as_float(b));
}

// ---------------- K0: init counts, fold We*a_e ------------------------------
__global__ void k_init(const float* __restrict__ We, const float* __restrict__ att) {
    int i = blockIdx.x * blockDim.x + threadIdx.x;
    if (i < N_NODES) g_cur[i] = 0;
    if (i == 0) g_off[N_NODES] = N_EDGES;
    if (i < 32) {
        int h = i & 3, c = i >> 2;
        float s = 0.0f;
        #pragma unroll
        for (int p = 0; p < 4; p++)
            s += __ldg(We + c * 16 + h * 4 + p) * __ldg(att + h * 68 + 64 + p);
        g_sew[c * 4 + h] = s;
    }
}

// ---------------- K1: histogram of dst --------------------------------------
__global__ void k_hist(const int* __restrict__ ei) {
    int e = blockIdx.x * blockDim.x + threadIdx.x;
    if (e < N_EDGES) atomicAdd(&g_cur[__ldg(ei + N_EDGES + e)], 1);
}

// ---------------- K2: exclusive scan (single block, 1024 threads) ----------
__global__ __launch_bounds__(1024) void k_scan() {
    __shared__ int part[1024];
    const int PER = (N_NODES + 1023) / 1024;
    int t = threadIdx.x;
    int base = t * PER;
    int s = 0;
    for (int i = 0; i < PER; i++) {
        int idx = base + i;
        if (idx < N_NODES) s += g_cur[idx];
    }
    part[t] = s;
    __syncthreads();
    for (int off = 1; off < 1024; off <<= 1) {
        int v = (t >= off) ? part[t - off] : 0;
        __syncthreads();
        part[t] += v;
        __syncthreads();
    }
    int run = part[t] - s;
    for (int i = 0; i < PER; i++) {
        int idx = base + i;
        if (idx < N_NODES) {
            int c = g_cur[idx];
            g_off[idx] = run;
            g_cur[idx] = run;
            run += c;
        }
    }
}

// ---------------- K3: GEMM xh = x @ W with f32x2 packed FMA -----------------
// Block 256 threads, tile 128 rows x 128 cols, KP=32 (4 phases).
// Thread: 4 rows x 16 cols. rows = lane*4 (conflict-free LDS.128 on x),
// cols = warp*16 (fully-broadcast LDS.128 on W). 32 FFMA2 = 64 FMA per k.
#define KP 32
#define XSTR 132
__global__ __launch_bounds__(256) void k_gemm(const float* __restrict__ x,
                                              const float* __restrict__ W) {
    __shared__ __align__(16) float sW[KP][128];
    __shared__ __align__(16) float sX[KP][XSTR];
    int t = threadIdx.x;
    int rg = (t & 31) * 4;   // 4 rows rg..rg+3
    int cg = (t >> 5) * 16;  // 16 cols cg..cg+15
    int blockRow = blockIdx.x * 128;

    unsigned long long acc[4][8];
    #pragma unroll
    for (int r = 0; r < 4; r++)
        #pragma unroll
        for (int p = 0; p < 8; p++) acc[r][p] = 0ULL;

    #pragma unroll
    for (int phase = 0; phase < 4; phase++) {
        int k0 = phase * KP;
        __syncthreads();
        // stage W[k0..k0+31][0..127]: 1024 float4, 4 per thread
        #pragma unroll
        for (int i = 0; i < 4; i++) {
            int idx = i * 256 + t;
            int k = idx >> 5, cc = idx & 31;
            *(float4*)&sW[k][cc * 4] =
                __ldg((const float4*)(W + (size_t)(k0 + k) * 128) + cc);
        }
        // stage x transposed: sX[k][row], 1024 float4, 4 per thread
        #pragma unroll
        for (int i = 0; i < 4; i++) {
            int idx = i * 256 + t;
            int row = idx >> 3, k4 = idx & 7;
            int gr = blockRow + row;
            if (gr >= N_NODES) gr = N_NODES - 1;
            float4 v = __ldg((const float4*)(x + (size_t)gr * 128 + k0) + k4);
            sX[k4 * 4 + 0][row] = v.x;
            sX[k4 * 4 + 1][row] = v.y;
            sX[k4 * 4 + 2][row] = v.z;
            sX[k4 * 4 + 3][row] = v.w;
        }
        __syncthreads();

        #pragma unroll
        for (int k = 0; k < KP; k++) {
            float4 xv = *(const float4*)&sX[k][rg];
            float4 w0 = *(const float4*)&sW[k][cg];
            float4 w1 = *(const float4*)&sW[k][cg + 4];
            float4 w2 = *(const float4*)&sW[k][cg + 8];
            float4 w3 = *(const float4*)&sW[k][cg + 12];
            unsigned long long wp[8];
            wp[0] = pack2(w0.x, w0.y); wp[1] = pack2(w0.z, w0.w);
            wp[2] = pack2(w1.x, w1.y); wp[3] = pack2(w1.z, w1.w);
            wp[4] = pack2(w2.x, w2.y); wp[5] = pack2(w2.z, w2.w);
            wp[6] = pack2(w3.x, w3.y); wp[7] = pack2(w3.z, w3.w);
            unsigned long long xb[4];
            xb[0] = bcast2(xv.x); xb[1] = bcast2(xv.y);
            xb[2] = bcast2(xv.z); xb[3] = bcast2(xv.w);
            #pragma unroll
            for (int r = 0; r < 4; r++)
                #pragma unroll
                for (int p = 0; p < 8; p++)
                    ffma2(acc[r][p], xb[r], wp[p]);
        }
    }

    #pragma unroll
    for (int r = 0; r < 4; r++) {
        int grow = blockRow + rg + r;
        if (grow >= N_NODES) continue;
        float* op = g_xh + (size_t)grow * 128 + cg;
        #pragma unroll
        for (int p = 0; p < 8; p += 2) {
            float2 lo = unpack2(acc[r][p]);
            float2 hi = unpack2(acc[r][p + 1]);
            *(float4*)(op + p * 2) = make_float4(lo.x, lo.y, hi.x, hi.y);
        }
    }
}

// ---------------- K3b: s_i, s_j = <xh[n,h,:], a_i/a_j> ----------------------
__global__ void k_sisj(const float* __restrict__ att) {
    int i = blockIdx.x * blockDim.x + threadIdx.x;  // node*4 + head
    if (i >= N_NODES * 4) return;
    int node = i >> 2, h = i & 3;
    const float4* xp = (const float4*)(g_xh + (size_t)node * 128 + h * 32);
    const float4* ai = (const float4*)(att + h * 68);
    const float4* aj = (const float4*)(att + h * 68 + 32);
    float si = 0.0f, sj = 0.0f;
    #pragma unroll
    for (int j = 0; j < 8; j++) {
        float4 v = __ldg(xp + j);
        float4 a = __ldg(ai + j);
        float4 b = __ldg(aj + j);
        si += v.x * a.x + v.y * a.y + v.z * a.z + v.w * a.w;
        sj += v.x * b.x + v.y * b.y + v.z * b.z + v.w * b.w;
    }
    g_si[i] = si;
    g_sj[i] = sj;
}

// ---------------- K4: edge logits -> exp, scatter into CSR ------------------
__global__ void k_edge(const int* __restrict__ ei, const float* __restrict__ eattr) {
    int e = blockIdx.x * blockDim.x + threadIdx.x;
    if (e >= N_EDGES) return;
    int src = __ldg(ei + e);
    int dst = __ldg(ei + N_EDGES + e);
    float4 f0 = __ldg((const float4*)eattr + (size_t)e * 2);
    float4 f1 = __ldg((const float4*)eattr + (size_t)e * 2 + 1);
    float f[8] = {f0.x, f0.y, f0.z, f0.w, f1.x, f1.y, f1.z, f1.w};
    float4 si = *(const float4*)(g_si + dst * 4);
    float4 sj = *(const float4*)(g_sj + src * 4);
    float sih[4] = {si.x, si.y, si.z, si.w};
    float sjh[4] = {sj.x, sj.y, sj.z, sj.w};
    float a[4];
    #pragma unroll
    for (int h = 0; h < 4; h++) {
        float se = 0.0f;
        #pragma unroll
        for (int c = 0; c < 8; c++) se += f[c] * g_sew[c * 4 + h];
        float v = sih[h] + sjh[h] + se;
        v = v > 0.0f ? v : NEG_SLOPE * v;
        a[h] = __expf(v);   // store exp directly (logits are O(1); no max shift needed)
    }
    int pos = atomicAdd(&g_cur[dst], 1);
    g_ssrc[pos] = src;
    *((float4*)g_salpha + pos) = make_float4(a[0], a[1], a[2], a[3]);
}

// ---------------- K5: warp-per-node aggregation ------------------------------
__global__ __launch_bounds__(256) void k_aggr(const float* __restrict__ bias,
                                              float* __restrict__ out) {
    int w = (blockIdx.x * blockDim.x + threadIdx.x) >> 5;
    if (w >= N_NODES) return;
    int lane = threadIdx.x & 31;
    int h = lane >> 3;

    int start = g_off[w];
    int end   = g_off[w + 1];

    float ax = 0.0f, ay = 0.0f, az = 0.0f, aw = 0.0f, den = 0.0f;

    #pragma unroll 4
    for (int e = start; e < end; e++) {
        int src = __ldg(&g_ssrc[e]);
        float ea = __ldg(&g_salpha[(size_t)e * 4 + h]);
        den += ea;
        float4 xv = __ldg((const float4*)(g_xh + (size_t)src * 128) + lane);
        ax += ea * xv.x; ay += ea * xv.y; az += ea * xv.z; aw += ea * xv.w;
    }

    float inv = 1.0f / (den + 1e-16f);
    float4 b = __ldg((const float4*)bias + lane);
    ((float4*)out)[(size_t)w * 32 + lane] =
        make_float4(ax * inv + b.x, ay * inv + b.y, az * inv + b.z, aw * inv + b.w);
}

// ---------------- launch ----------------------------------------------------
extern "C" void kernel_launch(void* const* d_in, const int* in_sizes, int n_in,
                              void* d_out, int out_size) {
    const float* x     = (const float*)d_in[0];
    const int*   ei    = (const int*)  d_in[1];
    const float* eattr = (const float*)d_in[2];
    const float* W     = (const float*)d_in[3];
    const float* We    = (const float*)d_in[4];
    const float* att   = (const float*)d_in[5];
    const float* bias  = (const float*)d_in[6];
    float* out = (float*)d_out;

    k_init <<<(N_NODES + 255) / 256, 256>>>(We, att);
    k_hist <<<(N_EDGES + 255) / 256, 256>>>(ei);
    k_scan <<<1, 1024>>>();
    k_gemm <<<(N_NODES + 127) / 128, 256>>>(x, W);
    k_sisj <<<(N_NODES * 4 + 255) / 256, 256>>>(att);
    k_edge <<<(N_EDGES + 255) / 256, 256>>>(ei, eattr);
    k_aggr <<<((size_t)N_NODES * 32 + 255) / 256, 256>>>(bias, out);
}

// round 11
// speedup vs baseline: 2.1143x; 1.5507x over previous
#include <cuda_runtime.h>

#define N_NODES 50000
#define N_EDGES 800000
#define NEG_SLOPE 0.2f
#define SCAN_B 196   // ceil(50000/256)

// ---------------- scratch (device globals) ---------------------------------
__device__ __align__(16) float g_xh[(size_t)N_NODES * 128]; // x @ W
__device__ __align__(16) float g_si[N_NODES * 4];           // <xh, a_i> per head
__device__ __align__(16) float g_sj[N_NODES * 4];           // <xh, a_j> per head
__device__ float g_sew[32];                                 // folded We * a_e  [c][h]
__device__ int   g_cur[N_NODES];                            // counts -> cursors
__device__ int   g_off[N_NODES + 1];                        // CSR offsets by dst
__device__ int   g_bsum[256];                               // per-block totals
__device__ int   g_bpre[256];                               // exclusive prefix of totals
__device__ int   g_ssrc[N_EDGES];                           // dst-sorted src ids
__device__ __align__(16) float g_salpha[(size_t)N_EDGES * 4]; // dst-sorted exp(logit)

// ---------------- f32x2 packed-FMA helpers (Blackwell FFMA2) ----------------
__device__ __forceinline__ void ffma2(unsigned long long& d,
                                      unsigned long long a,
                                      unsigned long long b) {
    asm("fma.rn.f32x2 %0, %1, %2, %0;" : "+l"(d) : "l"(a), "l"(b));
}
__device__ __forceinline__ unsigned long long bcast2(float x) {
    unsigned long long r;
    unsigned int u = __float_as_uint(x);
    asm("mov.b64 %0, {%1, %1};" : "=l"(r) : "r"(u));
    return r;
}
__device__ __forceinline__ float2 unpack2(unsigned long long v) {
    unsigned int a, b;
    asm("mov.b64 {%0, %1}, %2;" : "=r"(a), "=r"(b) : "l"(v));
    return make_float2(__uint_as_float(a), __uint_as_float(b));
}

// ---------------- K0: init counts, fold We*a_e ------------------------------
__global__ void k_init(const float* __restrict__ We, const float* __restrict__ att) {
    int i = blockIdx.x * blockDim.x + threadIdx.x;
    if (i < N_NODES) g_cur[i] = 0;
    if (i == 0) g_off[N_NODES] = N_EDGES;
    if (i < 32) {
        int h = i & 3, c = i >> 2;
        float s = 0.0f;
        #pragma unroll
        for (int p = 0; p < 4; p++)
            s += __ldg(We + c * 16 + h * 4 + p) * __ldg(att + h * 68 + 64 + p);
        g_sew[c * 4 + h] = s;
    }
}

// ---------------- K1: histogram of dst --------------------------------------
__global__ void k_hist(const int* __restrict__ ei) {
    int e = blockIdx.x * blockDim.x + threadIdx.x;
    if (e < N_EDGES) atomicAdd(&g_cur[__ldg(ei + N_EDGES + e)], 1);
}

// ---------------- K2a: per-block local exclusive scan + block total ---------
__global__ __launch_bounds__(256) void k_scanA() {
    __shared__ int sh[256];
    int t = threadIdx.x;
    int i = blockIdx.x * 256 + t;
    int c = (i < N_NODES) ? g_cur[i] : 0;
    sh[t] = c;
    __syncthreads();
    int own = c;
    #pragma unroll
    for (int off = 1; off < 256; off <<= 1) {
        int v = (t >= off) ? sh[t - off] : 0;
        __syncthreads();
        sh[t] += v;
        __syncthreads();
    }
    if (i < N_NODES) g_off[i] = sh[t] - own;  // local exclusive prefix
    if (t == 255) g_bsum[blockIdx.x] = sh[255];
}

// ---------------- K2b: scan the block totals (1 block) ----------------------
__global__ __launch_bounds__(256) void k_scanB() {
    __shared__ int sh[256];
    int t = threadIdx.x;
    int v = (t < SCAN_B) ? g_bsum[t] : 0;
    sh[t] = v;
    __syncthreads();
    int own = v;
    #pragma unroll
    for (int off = 1; off < 256; off <<= 1) {
        int u = (t >= off) ? sh[t - off] : 0;
        __syncthreads();
        sh[t] += u;
        __syncthreads();
    }
    g_bpre[t] = sh[t] - own;
}

// ---------------- K2c: add block prefix, init cursors ------------------------
__global__ __launch_bounds__(256) void k_scanC() {
    int i = blockIdx.x * 256 + threadIdx.x;
    if (i >= N_NODES) return;
    int off = g_off[i] + g_bpre[blockIdx.x];
    g_off[i] = off;
    g_cur[i] = off;
}

// ---------------- K3: GEMM xh = x @ W with f32x2 packed FMA -----------------
// Block 256 threads, tile 128 rows x 128 cols, KP=32 (4 phases).
// Thread: 4 rows x 16 cols. W pairs loaded directly as u64 (no pack MOVs).
#define KP 32
#define XSTR 132
__global__ __launch_bounds__(256, 2) void k_gemm(const float* __restrict__ x,
                                                 const float* __restrict__ W) {
    __shared__ __align__(16) float sW[KP][128];
    __shared__ __align__(16) float sX[KP][XSTR];
    int t = threadIdx.x;
    int rg = (t & 31) * 4;   // 4 rows rg..rg+3
    int cg = (t >> 5) * 16;  // 16 cols cg..cg+15
    int blockRow = blockIdx.x * 128;

    unsigned long long acc[4][8];
    #pragma unroll
    for (int r = 0; r < 4; r++)
        #pragma unroll
        for (int p = 0; p < 8; p++) acc[r][p] = 0ULL;

    #pragma unroll
    for (int phase = 0; phase < 4; phase++) {
        int k0 = phase * KP;
        __syncthreads();
        // stage W[k0..k0+31][0..127]: 1024 float4, 4 per thread
        #pragma unroll
        for (int i = 0; i < 4; i++) {
            int idx = i * 256 + t;
            int k = idx >> 5, cc = idx & 31;
            *(float4*)&sW[k][cc * 4] =
                __ldg((const float4*)(W + (size_t)(k0 + k) * 128) + cc);
        }
        // stage x transposed: sX[k][row], 1024 float4, 4 per thread
        #pragma unroll
        for (int i = 0; i < 4; i++) {
            int idx = i * 256 + t;
            int row = idx >> 3, k4 = idx & 7;
            int gr = blockRow + row;
            if (gr >= N_NODES) gr = N_NODES - 1;
            float4 v = __ldg((const float4*)(x + (size_t)gr * 128 + k0) + k4);
            sX[k4 * 4 + 0][row] = v.x;
            sX[k4 * 4 + 1][row] = v.y;
            sX[k4 * 4 + 2][row] = v.z;
            sX[k4 * 4 + 3][row] = v.w;
        }
        __syncthreads();

        #pragma unroll
        for (int k = 0; k < KP; k++) {
            float4 xv = *(const float4*)&sX[k][rg];
            const ulonglong2* wq = (const ulonglong2*)&sW[k][cg];
            ulonglong2 q0 = wq[0], q1 = wq[1], q2 = wq[2], q3 = wq[3];
            unsigned long long xb[4];
            xb[0] = bcast2(xv.x); xb[1] = bcast2(xv.y);
            xb[2] = bcast2(xv.z); xb[3] = bcast2(xv.w);
            #pragma unroll
            for (int r = 0; r < 4; r++) {
                ffma2(acc[r][0], xb[r], q0.x);
                ffma2(acc[r][1], xb[r], q0.y);
                ffma2(acc[r][2], xb[r], q1.x);
                ffma2(acc[r][3], xb[r], q1.y);
                ffma2(acc[r][4], xb[r], q2.x);
                ffma2(acc[r][5], xb[r], q2.y);
                ffma2(acc[r][6], xb[r], q3.x);
                ffma2(acc[r][7], xb[r], q3.y);
            }
        }
    }

    #pragma unroll
    for (int r = 0; r < 4; r++) {
        int grow = blockRow + rg + r;
        if (grow >= N_NODES) continue;
        float* op = g_xh + (size_t)grow * 128 + cg;
        #pragma unroll
        for (int p = 0; p < 8; p += 2) {
            float2 lo = unpack2(acc[r][p]);
            float2 hi = unpack2(acc[r][p + 1]);
            *(float4*)(op + p * 2) = make_float4(lo.x, lo.y, hi.x, hi.y);
        }
    }
}

// ---------------- K3b: s_i, s_j = <xh[n,h,:], a_i/a_j> ----------------------
__global__ void k_sisj(const float* __restrict__ att) {
    int i = blockIdx.x * blockDim.x + threadIdx.x;  // node*4 + head
    if (i >= N_NODES * 4) return;
    int node = i >> 2, h = i & 3;
    const float4* xp = (const float4*)(g_xh + (size_t)node * 128 + h * 32);
    const float4* ai = (const float4*)(att + h * 68);
    const float4* aj = (const float4*)(att + h * 68 + 32);
    float si = 0.0f, sj = 0.0f;
    #pragma unroll
    for (int j = 0; j < 8; j++) {
        float4 v = __ldg(xp + j);
        float4 a = __ldg(ai + j);
        float4 b = __ldg(aj + j);
        si += v.x * a.x + v.y * a.y + v.z * a.z + v.w * a.w;
        sj += v.x * b.x + v.y * b.y + v.z * b.z + v.w * b.w;
    }
    g_si[i] = si;
    g_sj[i] = sj;
}

// ---------------- K4: edge logits -> exp, scatter into CSR ------------------
__global__ void k_edge(const int* __restrict__ ei, const float* __restrict__ eattr) {
    int e = blockIdx.x * blockDim.x + threadIdx.x;
    if (e >= N_EDGES) return;
    int src = __ldg(ei + e);
    int dst = __ldg(ei + N_EDGES + e);
    float4 f0 = __ldg((const float4*)eattr + (size_t)e * 2);
    float4 f1 = __ldg((const float4*)eattr + (size_t)e * 2 + 1);
    float f[8] = {f0.x, f0.y, f0.z, f0.w, f1.x, f1.y, f1.z, f1.w};
    float4 si = *(const float4*)(g_si + dst * 4);
    float4 sj = *(const float4*)(g_sj + src * 4);
    float sih[4] = {si.x, si.y, si.z, si.w};
    float sjh[4] = {sj.x, sj.y, sj.z, sj.w};
    float a[4];
    #pragma unroll
    for (int h = 0; h < 4; h++) {
        float se = 0.0f;
        #pragma unroll
        for (int c = 0; c < 8; c++) se += f[c] * g_sew[c * 4 + h];
        float v = sih[h] + sjh[h] + se;
        v = v > 0.0f ? v : NEG_SLOPE * v;
        a[h] = __expf(v);   // logits are O(1); exp without max shift is safe in fp32
    }
    int pos = atomicAdd(&g_cur[dst], 1);
    g_ssrc[pos] = src;
    *((float4*)g_salpha + pos) = make_float4(a[0], a[1], a[2], a[3]);
}

// ---------------- K5: warp-per-node aggregation ------------------------------
__global__ __launch_bounds__(256) void k_aggr(const float* __restrict__ bias,
                                              float* __restrict__ out) {
    int w = (blockIdx.x * blockDim.x + threadIdx.x) >> 5;
    if (w >= N_NODES) return;
    int lane = threadIdx.x & 31;
    int h = lane >> 3;

    int start = g_off[w];
    int end   = g_off[w + 1];

    float ax = 0.0f, ay = 0.0f, az = 0.0f, aw = 0.0f, den = 0.0f;

    #pragma unroll 4
    for (int e = start; e < end; e++) {
        int src = __ldg(&g_ssrc[e]);
        float ea = __ldg(&g_salpha[(size_t)e * 4 + h]);
        den += ea;
        float4 xv = __ldg((const float4*)(g_xh + (size_t)src * 128) + lane);
        ax += ea * xv.x; ay += ea * xv.y; az += ea * xv.z; aw += ea * xv.w;
    }

    float inv = 1.0f / (den + 1e-16f);
    float4 b = __ldg((const float4*)bias + lane);
    ((float4*)out)[(size_t)w * 32 + lane] =
        make_float4(ax * inv + b.x, ay * inv + b.y, az * inv + b.z, aw * inv + b.w);
}

// ---------------- launch ----------------------------------------------------
extern "C" void kernel_launch(void* const* d_in, const int* in_sizes, int n_in,
                              void* d_out, int out_size) {
    const float* x     = (const float*)d_in[0];
    const int*   ei    = (const int*)  d_in[1];
    const float* eattr = (const float*)d_in[2];
    const float* W     = (const float*)d_in[3];
    const float* We    = (const float*)d_in[4];
    const float* att   = (const float*)d_in[5];
    const float* bias  = (const float*)d_in[6];
    float* out = (float*)d_out;

    k_init <<<(N_NODES + 255) / 256, 256>>>(We, att);
    k_hist <<<(N_EDGES + 255) / 256, 256>>>(ei);
    k_scanA<<<SCAN_B, 256>>>();
    k_scanB<<<1, 256>>>();
    k_scanC<<<SCAN_B, 256>>>();
    k_gemm <<<(N_NODES + 127) / 128, 256>>>(x, W);
    k_sisj <<<(N_NODES * 4 + 255) / 256, 256>>>(att);
    k_edge <<<(N_EDGES + 255) / 256, 256>>>(ei, eattr);
    k_aggr <<<((size_t)N_NODES * 32 + 255) / 256, 256>>>(bias, out);
}

// round 12
// speedup vs baseline: 2.3830x; 1.1271x over previous
#include <cuda_runtime.h>
#include <cuda_fp16.h>

#define N_NODES 50000
#define N_EDGES 800000
#define NEG_SLOPE 0.2f
#define SCAN_B 196   // ceil(50000/256)

// ---------------- scratch (device globals) ---------------------------------
__device__ __align__(16) __half g_xh16[(size_t)N_NODES * 128]; // x @ W in fp16
__device__ __align__(16) float g_si[N_NODES * 4];           // <xh, a_i> per head
__device__ __align__(16) float g_sj[N_NODES * 4];           // <xh, a_j> per head
__device__ float g_sew[32];                                 // folded We * a_e  [c][h]
__device__ int   g_cur[N_NODES];                            // counts -> cursors
__device__ int   g_off[N_NODES + 1];                        // CSR offsets by dst
__device__ int   g_bsum[256];                               // per-block totals
__device__ int   g_ssrc[N_EDGES];                           // dst-sorted src ids
__device__ __align__(16) float g_salpha[(size_t)N_EDGES * 4]; // dst-sorted exp(logit)

// ---------------- f32x2 packed-FMA helpers (Blackwell FFMA2) ----------------
__device__ __forceinline__ void ffma2(unsigned long long& d,
                                      unsigned long long a,
                                      unsigned long long b) {
    asm("fma.rn.f32x2 %0, %1, %2, %0;" : "+l"(d) : "l"(a), "l"(b));
}
__device__ __forceinline__ unsigned long long bcast2(float x) {
    unsigned long long r;
    unsigned int u = __float_as_uint(x);
    asm("mov.b64 %0, {%1, %1};" : "=l"(r) : "r"(u));
    return r;
}
__device__ __forceinline__ float2 unpack2(unsigned long long v) {
    unsigned int a, b;
    asm("mov.b64 {%0, %1}, %2;" : "=r"(a), "=r"(b) : "l"(v));
    return make_float2(__uint_as_float(a), __uint_as_float(b));
}

// ---------------- K0: init counts, fold We*a_e ------------------------------
__global__ void k_init(const float* __restrict__ We, const float* __restrict__ att) {
    int i = blockIdx.x * blockDim.x + threadIdx.x;
    if (i < N_NODES) g_cur[i] = 0;
    if (i == 0) g_off[N_NODES] = N_EDGES;
    if (i < 32) {
        int h = i & 3, c = i >> 2;
        float s = 0.0f;
        #pragma unroll
        for (int p = 0; p < 4; p++)
            s += __ldg(We + c * 16 + h * 4 + p) * __ldg(att + h * 68 + 64 + p);
        g_sew[c * 4 + h] = s;
    }
}

// ---------------- K1: histogram of dst --------------------------------------
__global__ void k_hist(const int* __restrict__ ei) {
    int e = blockIdx.x * blockDim.x + threadIdx.x;
    if (e < N_EDGES) atomicAdd(&g_cur[__ldg(ei + N_EDGES + e)], 1);
}

// ---------------- K2a: per-block local exclusive scan + block total ---------
__global__ __launch_bounds__(256) void k_scanA() {
    __shared__ int sh[256];
    int t = threadIdx.x;
    int i = blockIdx.x * 256 + t;
    int c = (i < N_NODES) ? g_cur[i] : 0;
    sh[t] = c;
    __syncthreads();
    int own = c;
    #pragma unroll
    for (int off = 1; off < 256; off <<= 1) {
        int v = (t >= off) ? sh[t - off] : 0;
        __syncthreads();
        sh[t] += v;
        __syncthreads();
    }
    if (i < N_NODES) g_off[i] = sh[t] - own;  // local exclusive prefix
    if (t == 255) g_bsum[blockIdx.x] = sh[255];
}

// ---------------- K2b: add block prefix (self-computed), init cursors -------
__global__ __launch_bounds__(256) void k_scanC() {
    __shared__ int sh[256];
    int t = threadIdx.x;
    sh[t] = (t < blockIdx.x) ? g_bsum[t] : 0;
    __syncthreads();
    #pragma unroll
    for (int off = 128; off > 0; off >>= 1) {
        if (t < off) sh[t] += sh[t + off];
        __syncthreads();
    }
    int pre = sh[0];
    int i = blockIdx.x * 256 + t;
    if (i < N_NODES) {
        int off = g_off[i] + pre;
        g_off[i] = off;
        g_cur[i] = off;
    }
}

// ---------------- K3: GEMM xh = x @ W (f32x2 FMA) + fused s_i/s_j -----------
// Block 256 threads, tile 128 rows x 128 cols, KP=32 (4 phases).
// Thread: 4 rows x 16 cols. Output written as fp16. s_i/s_j reduced via smem.
#define KP 32
#define XSTR 132
__global__ __launch_bounds__(256, 2) void k_gemm(const float* __restrict__ x,
                                                 const float* __restrict__ W,
                                                 const float* __restrict__ att) {
    __shared__ __align__(16) float sW[KP][128];
    __shared__ __align__(16) float sX[KP][XSTR];
    __shared__ float sSi[8][32][4];
    __shared__ float sSj[8][32][4];
    int t = threadIdx.x;
    int lane = t & 31;
    int warp = t >> 5;
    int rg = lane * 4;       // 4 rows rg..rg+3
    int cg = warp * 16;      // 16 cols cg..cg+15
    int blockRow = blockIdx.x * 128;

    unsigned long long acc[4][8];
    #pragma unroll
    for (int r = 0; r < 4; r++)
        #pragma unroll
        for (int p = 0; p < 8; p++) acc[r][p] = 0ULL;

    #pragma unroll
    for (int phase = 0; phase < 4; phase++) {
        int k0 = phase * KP;
        __syncthreads();
        // stage W[k0..k0+31][0..127]: 1024 float4, 4 per thread
        #pragma unroll
        for (int i = 0; i < 4; i++) {
            int idx = i * 256 + t;
            int k = idx >> 5, cc = idx & 31;
            *(float4*)&sW[k][cc * 4] =
                __ldg((const float4*)(W + (size_t)(k0 + k) * 128) + cc);
        }
        // stage x transposed: sX[k][row], 1024 float4, 4 per thread
        #pragma unroll
        for (int i = 0; i < 4; i++) {
            int idx = i * 256 + t;
            int row = idx >> 3, k4 = idx & 7;
            int gr = blockRow + row;
            if (gr >= N_NODES) gr = N_NODES - 1;
            float4 v = __ldg((const float4*)(x + (size_t)gr * 128 + k0) + k4);
            sX[k4 * 4 + 0][row] = v.x;
            sX[k4 * 4 + 1][row] = v.y;
            sX[k4 * 4 + 2][row] = v.z;
            sX[k4 * 4 + 3][row] = v.w;
        }
        __syncthreads();

        #pragma unroll
        for (int k = 0; k < KP; k++) {
            float4 xv = *(const float4*)&sX[k][rg];
            const ulonglong2* wq = (const ulonglong2*)&sW[k][cg];
            ulonglong2 q0 = wq[0], q1 = wq[1], q2 = wq[2], q3 = wq[3];
            unsigned long long xb[4];
            xb[0] = bcast2(xv.x); xb[1] = bcast2(xv.y);
            xb[2] = bcast2(xv.z); xb[3] = bcast2(xv.w);
            #pragma unroll
            for (int r = 0; r < 4; r++) {
                ffma2(acc[r][0], xb[r], q0.x);
                ffma2(acc[r][1], xb[r], q0.y);
                ffma2(acc[r][2], xb[r], q1.x);
                ffma2(acc[r][3], xb[r], q1.y);
                ffma2(acc[r][4], xb[r], q2.x);
                ffma2(acc[r][5], xb[r], q2.y);
                ffma2(acc[r][6], xb[r], q3.x);
                ffma2(acc[r][7], xb[r], q3.y);
            }
        }
    }

    // ---- epilogue: fp16 store + per-thread si/sj partials ----
    int h  = warp >> 1;          // head of this 16-col strip
    int cb = cg & 31;            // offset within head (0 or 16)
    const float* ai = att + h * 68 + cb;
    const float* aj = att + h * 68 + 32 + cb;
    float psi[4] = {0, 0, 0, 0}, psj[4] = {0, 0, 0, 0};

    #pragma unroll
    for (int r = 0; r < 4; r++) {
        int grow = blockRow + rg + r;
        __half2 hh[8];
        #pragma unroll
        for (int p = 0; p < 8; p++) {
            float2 f = unpack2(acc[r][p]);
            hh[p] = __floats2half2_rn(f.x, f.y);
            float a0 = __ldg(ai + 2 * p), a1 = __ldg(ai + 2 * p + 1);
            float b0 = __ldg(aj + 2 * p), b1 = __ldg(aj + 2 * p + 1);
            psi[r] += f.x * a0 + f.y * a1;
            psj[r] += f.x * b0 + f.y * b1;
        }
        if (grow < N_NODES) {
            uint4 v0, v1;
            v0.x = *(unsigned*)&hh[0]; v0.y = *(unsigned*)&hh[1];
            v0.z = *(unsigned*)&hh[2]; v0.w = *(unsigned*)&hh[3];
            v1.x = *(unsigned*)&hh[4]; v1.y = *(unsigned*)&hh[5];
            v1.z = *(unsigned*)&hh[6]; v1.w = *(unsigned*)&hh[7];
            uint4* dst = (uint4*)(g_xh16 + (size_t)grow * 128 + cg);
            dst[0] = v0; dst[1] = v1;
        }
        sSi[warp][lane][r] = psi[r];
        sSj[warp][lane][r] = psj[r];
    }
    __syncthreads();

    // combine the two 16-col halves of each head: 512 (row, head) pairs
    #pragma unroll
    for (int ii = 0; ii < 2; ii++) {
        int idx = t + ii * 256;       // idx = h2*128 + R
        int h2 = idx >> 7, R = idx & 127;
        float si = sSi[2 * h2][R >> 2][R & 3] + sSi[2 * h2 + 1][R >> 2][R & 3];
        float sj = sSj[2 * h2][R >> 2][R & 3] + sSj[2 * h2 + 1][R >> 2][R & 3];
        int grow = blockRow + R;
        if (grow < N_NODES) {
            g_si[grow * 4 + h2] = si;
            g_sj[grow * 4 + h2] = sj;
        }
    }
}

// ---------------- K4: edge logits -> exp, scatter into CSR ------------------
__global__ void k_edge(const int* __restrict__ ei, const float* __restrict__ eattr) {
    int e = blockIdx.x * blockDim.x + threadIdx.x;
    if (e >= N_EDGES) return;
    int src = __ldg(ei + e);
    int dst = __ldg(ei + N_EDGES + e);
    float4 f0 = __ldg((const float4*)eattr + (size_t)e * 2);
    float4 f1 = __ldg((const float4*)eattr + (size_t)e * 2 + 1);
    float f[8] = {f0.x, f0.y, f0.z, f0.w, f1.x, f1.y, f1.z, f1.w};
    float4 si = *(const float4*)(g_si + dst * 4);
    float4 sj = *(const float4*)(g_sj + src * 4);
    float sih[4] = {si.x, si.y, si.z, si.w};
    float sjh[4] = {sj.x, sj.y, sj.z, sj.w};
    float a[4];
    #pragma unroll
    for (int h = 0; h < 4; h++) {
        float se = 0.0f;
        #pragma unroll
        for (int c = 0; c < 8; c++) se += f[c] * g_sew[c * 4 + h];
        float v = sih[h] + sjh[h] + se;
        v = v > 0.0f ? v : NEG_SLOPE * v;
        a[h] = __expf(v);   // logits are O(1); exp without max shift is safe in fp32
    }
    int pos = atomicAdd(&g_cur[dst], 1);
    g_ssrc[pos] = src;
    *((float4*)g_salpha + pos) = make_float4(a[0], a[1], a[2], a[3]);
}

// ---------------- K5: warp-per-node aggregation (fp16 gather) ----------------
__global__ __launch_bounds__(256) void k_aggr(const float* __restrict__ bias,
                                              float* __restrict__ out) {
    int w = (blockIdx.x * blockDim.x + threadIdx.x) >> 5;
    if (w >= N_NODES) return;
    int lane = threadIdx.x & 31;
    int h = lane >> 3;

    int start = g_off[w];
    int end   = g_off[w + 1];

    float ax = 0.0f, ay = 0.0f, az = 0.0f, aw = 0.0f, den = 0.0f;

    #pragma unroll 4
    for (int e = start; e < end; e++) {
        int src = __ldg(&g_ssrc[e]);
        float ea = __ldg(&g_salpha[(size_t)e * 4 + h]);
        den += ea;
        uint2 u = __ldg((const uint2*)(g_xh16 + (size_t)src * 128) + lane);
        float2 f0 = __half22float2(*(__half2*)&u.x);
        float2 f1 = __half22float2(*(__half2*)&u.y);
        ax += ea * f0.x; ay += ea * f0.y; az += ea * f1.x; aw += ea * f1.y;
    }

    float inv = 1.0f / (den + 1e-16f);
    float4 b = __ldg((const float4*)bias + lane);
    ((float4*)out)[(size_t)w * 32 + lane] =
        make_float4(ax * inv + b.x, ay * inv + b.y, az * inv + b.z, aw * inv + b.w);
}

// ---------------- launch ----------------------------------------------------
extern "C" void kernel_launch(void* const* d_in, const int* in_sizes, int n_in,
                              void* d_out, int out_size) {
    const float* x     = (const float*)d_in[0];
    const int*   ei    = (const int*)  d_in[1];
    const float* eattr = (const float*)d_in[2];
    const float* W     = (const float*)d_in[3];
    const float* We    = (const float*)d_in[4];
    const float* att   = (const float*)d_in[5];
    const float* bias  = (const float*)d_in[6];
    float* out = (float*)d_out;

    k_init <<<(N_NODES + 255) / 256, 256>>>(We, att);
    k_hist <<<(N_EDGES + 255) / 256, 256>>>(ei);
    k_scanA<<<SCAN_B, 256>>>();
    k_scanC<<<SCAN_B, 256>>>();
    k_gemm <<<(N_NODES + 127) / 128, 256>>>(x, W, att);
    k_edge <<<(N_EDGES + 255) / 256, 256>>>(ei, eattr);
    k_aggr <<<((size_t)N_NODES * 32 + 255) / 256, 256>>>(bias, out);
}

// round 13
// speedup vs baseline: 2.4244x; 1.0174x over previous
#include <cuda_runtime.h>
#include <cuda_fp16.h>

#define N_NODES 50000
#define N_EDGES 800000
#define NEG_SLOPE 0.2f
#define SCAN_B 196          // ceil(50000/256)
#define GEMM_B 391          // ceil(50000/128)
#define HIST_B 196

// ---------------- scratch (device globals) ---------------------------------
__device__ __align__(16) __half g_xh16[(size_t)N_NODES * 128]; // x @ W in fp16
__device__ __align__(16) float g_si[N_NODES * 4];
__device__ __align__(16) float g_sj[N_NODES * 4];
__device__ float g_sew[32];                                 // folded We * a_e  [c][h]
__device__ int   g_cur[N_NODES];                            // counts -> cursors
__device__ int   g_off[N_NODES + 1];                        // CSR offsets by dst
__device__ unsigned long long g_state[SCAN_B];              // lookback scan state
__device__ int   g_ssrc[N_EDGES];                           // dst-sorted src ids
__device__ __align__(16) float g_salpha[(size_t)N_EDGES * 4]; // dst-sorted exp(logit)

// ---------------- f32x2 packed-FMA helpers (Blackwell FFMA2) ----------------
__device__ __forceinline__ void ffma2(unsigned long long& d,
                                      unsigned long long a,
                                      unsigned long long b) {
    asm("fma.rn.f32x2 %0, %1, %2, %0;" : "+l"(d) : "l"(a), "l"(b));
}
__device__ __forceinline__ unsigned long long bcast2(float x) {
    unsigned long long r;
    unsigned int u = __float_as_uint(x);
    asm("mov.b64 %0, {%1, %1};" : "=l"(r) : "r"(u));
    return r;
}
__device__ __forceinline__ float2 unpack2(unsigned long long v) {
    unsigned int a, b;
    asm("mov.b64 {%0, %1}, %2;" : "=r"(a), "=r"(b) : "l"(v));
    return make_float2(__uint_as_float(a), __uint_as_float(b));
}

// ---------------- K0: init counts, scan state, fold We*a_e ------------------
__global__ void k_init(const float* __restrict__ We, const float* __restrict__ att) {
    int i = blockIdx.x * blockDim.x + threadIdx.x;
    if (i < N_NODES) g_cur[i] = 0;
    if (i < SCAN_B) g_state[i] = 0ULL;
    if (i == 0) g_off[N_NODES] = N_EDGES;
    if (i < 32) {
        int h = i & 3, c = i >> 2;
        float s = 0.0f;
        #pragma unroll
        for (int p = 0; p < 4; p++)
            s += __ldg(We + c * 16 + h * 4 + p) * __ldg(att + h * 68 + 64 + p);
        g_sew[c * 4 + h] = s;
    }
}

// ---------------- K1: heterogeneous grid: GEMM tiles + dst histogram --------
// Blocks [0, GEMM_B): 128x128 GEMM tile (f32x2 FMA), fp16 output, fused si/sj.
// Blocks [GEMM_B, GEMM_B+HIST_B): histogram of dst into g_cur.
#define KP 32
#define XSTR 132
__global__ __launch_bounds__(256, 2) void k_gemm_hist(const float* __restrict__ x,
                                                      const float* __restrict__ W,
                                                      const float* __restrict__ att,
                                                      const int* __restrict__ ei) {
    __shared__ __align__(16) float sW[KP][128];
    __shared__ __align__(16) float sX[KP][XSTR];
    __shared__ float sSi[8][32][4];
    __shared__ float sSj[8][32][4];
    int t = threadIdx.x;

    if (blockIdx.x >= GEMM_B) {
        // ---- histogram part ----
        int base = (blockIdx.x - GEMM_B) * 256 + t;
        const int stride = HIST_B * 256;          // 50176
        #pragma unroll 4
        for (int e = base; e < N_EDGES; e += stride)
            atomicAdd(&g_cur[__ldg(ei + N_EDGES + e)], 1);
        return;
    }

    // ---- GEMM part ----
    int lane = t & 31;
    int warp = t >> 5;
    int rg = lane * 4;       // 4 rows rg..rg+3
    int cg = warp * 16;      // 16 cols cg..cg+15
    int blockRow = blockIdx.x * 128;

    unsigned long long acc[4][8];
    #pragma unroll
    for (int r = 0; r < 4; r++)
        #pragma unroll
        for (int p = 0; p < 8; p++) acc[r][p] = 0ULL;

    #pragma unroll
    for (int phase = 0; phase < 4; phase++) {
        int k0 = phase * KP;
        __syncthreads();
        #pragma unroll
        for (int i = 0; i < 4; i++) {
            int idx = i * 256 + t;
            int k = idx >> 5, cc = idx & 31;
            *(float4*)&sW[k][cc * 4] =
                __ldg((const float4*)(W + (size_t)(k0 + k) * 128) + cc);
        }
        #pragma unroll
        for (int i = 0; i < 4; i++) {
            int idx = i * 256 + t;
            int row = idx >> 3, k4 = idx & 7;
            int gr = blockRow + row;
            if (gr >= N_NODES) gr = N_NODES - 1;
            float4 v = __ldg((const float4*)(x + (size_t)gr * 128 + k0) + k4);
            sX[k4 * 4 + 0][row] = v.x;
            sX[k4 * 4 + 1][row] = v.y;
            sX[k4 * 4 + 2][row] = v.z;
            sX[k4 * 4 + 3][row] = v.w;
        }
        __syncthreads();

        #pragma unroll
        for (int k = 0; k < KP; k++) {
            float4 xv = *(const float4*)&sX[k][rg];
            const ulonglong2* wq = (const ulonglong2*)&sW[k][cg];
            ulonglong2 q0 = wq[0], q1 = wq[1], q2 = wq[2], q3 = wq[3];
            unsigned long long xb[4];
            xb[0] = bcast2(xv.x); xb[1] = bcast2(xv.y);
            xb[2] = bcast2(xv.z); xb[3] = bcast2(xv.w);
            #pragma unroll
            for (int r = 0; r < 4; r++) {
                ffma2(acc[r][0], xb[r], q0.x);
                ffma2(acc[r][1], xb[r], q0.y);
                ffma2(acc[r][2], xb[r], q1.x);
                ffma2(acc[r][3], xb[r], q1.y);
                ffma2(acc[r][4], xb[r], q2.x);
                ffma2(acc[r][5], xb[r], q2.y);
                ffma2(acc[r][6], xb[r], q3.x);
                ffma2(acc[r][7], xb[r], q3.y);
            }
        }
    }

    // ---- epilogue: fp16 store + per-thread si/sj partials ----
    int h  = warp >> 1;
    int cb = cg & 31;
    const float* ai = att + h * 68 + cb;
    const float* aj = att + h * 68 + 32 + cb;

    #pragma unroll
    for (int r = 0; r < 4; r++) {
        int grow = blockRow + rg + r;
        __half2 hh[8];
        float psi = 0.0f, psj = 0.0f;
        #pragma unroll
        for (int p = 0; p < 8; p++) {
            float2 f = unpack2(acc[r][p]);
            hh[p] = __floats2half2_rn(f.x, f.y);
            float a0 = __ldg(ai + 2 * p), a1 = __ldg(ai + 2 * p + 1);
            float b0 = __ldg(aj + 2 * p), b1 = __ldg(aj + 2 * p + 1);
            psi += f.x * a0 + f.y * a1;
            psj += f.x * b0 + f.y * b1;
        }
        if (grow < N_NODES) {
            uint4 v0, v1;
            v0.x = *(unsigned*)&hh[0]; v0.y = *(unsigned*)&hh[1];
            v0.z = *(unsigned*)&hh[2]; v0.w = *(unsigned*)&hh[3];
            v1.x = *(unsigned*)&hh[4]; v1.y = *(unsigned*)&hh[5];
            v1.z = *(unsigned*)&hh[6]; v1.w = *(unsigned*)&hh[7];
            uint4* dst = (uint4*)(g_xh16 + (size_t)grow * 128 + cg);
            dst[0] = v0; dst[1] = v1;
        }
        sSi[warp][lane][r] = psi;
        sSj[warp][lane][r] = psj;
    }
    __syncthreads();

    #pragma unroll
    for (int ii = 0; ii < 2; ii++) {
        int idx = t + ii * 256;       // idx = h2*128 + R
        int h2 = idx >> 7, R = idx & 127;
        float si = sSi[2 * h2][R >> 2][R & 3] + sSi[2 * h2 + 1][R >> 2][R & 3];
        float sj = sSj[2 * h2][R >> 2][R & 3] + sSj[2 * h2 + 1][R >> 2][R & 3];
        int grow = blockRow + R;
        if (grow < N_NODES) {
            g_si[grow * 4 + h2] = si;
            g_sj[grow * 4 + h2] = sj;
        }
    }
}

// ---------------- K2: single-pass decoupled-lookback scan -------------------
// state[b]: bits[63:62] = 0 none / 1 aggregate / 2 inclusive-prefix; low 32 = value
__global__ __launch_bounds__(256) void k_scan() {
    __shared__ int sh[256];
    __shared__ int s_excl;
    int t = threadIdx.x, b = blockIdx.x;
    int i = b * 256 + t;
    int c = (i < N_NODES) ? g_cur[i] : 0;
    sh[t] = c;
    __syncthreads();
    int own = c;
    #pragma unroll
    for (int off = 1; off < 256; off <<= 1) {
        int v = (t >= off) ? sh[t - off] : 0;
        __syncthreads();
        sh[t] += v;
        __syncthreads();
    }
    int total = sh[255];

    if (t == 0) {
        if (b == 0) {
            s_excl = 0;
            atomicExch(&g_state[0], (2ULL << 62) | (unsigned)total);
        } else {
            atomicExch(&g_state[b], (1ULL << 62) | (unsigned)total);
            long long run = 0;
            int j = b - 1;
            while (true) {
                unsigned long long s;
                do { s = atomicAdd(&g_state[j], 0ULL); } while ((s >> 62) == 0ULL);
                run += (long long)(s & 0xffffffffULL);
                if ((s >> 62) == 2ULL) break;
                j--;
            }
            s_excl = (int)run;
            atomicExch(&g_state[b], (2ULL << 62) | (unsigned)(run + total));
        }
    }
    __syncthreads();
    int pre = s_excl;
    if (i < N_NODES) {
        int o = sh[t] - own + pre;
        g_off[i] = o;
        g_cur[i] = o;
    }
}

// ---------------- K3: edge logits -> exp, scatter into CSR ------------------
__global__ void k_edge(const int* __restrict__ ei, const float* __restrict__ eattr) {
    int e = blockIdx.x * blockDim.x + threadIdx.x;
    if (e >= N_EDGES) return;
    int src = __ldg(ei + e);
    int dst = __ldg(ei + N_EDGES + e);
    float4 f0 = __ldg((const float4*)eattr + (size_t)e * 2);
    float4 f1 = __ldg((const float4*)eattr + (size_t)e * 2 + 1);
    float f[8] = {f0.x, f0.y, f0.z, f0.w, f1.x, f1.y, f1.z, f1.w};
    float4 si = *(const float4*)(g_si + dst * 4);
    float4 sj = *(const float4*)(g_sj + src * 4);
    float sih[4] = {si.x, si.y, si.z, si.w};
    float sjh[4] = {sj.x, sj.y, sj.z, sj.w};
    float a[4];
    #pragma unroll
    for (int h = 0; h < 4; h++) {
        float se = 0.0f;
        #pragma unroll
        for (int c = 0; c < 8; c++) se += f[c] * g_sew[c * 4 + h];
        float v = sih[h] + sjh[h] + se;
        v = v > 0.0f ? v : NEG_SLOPE * v;
        a[h] = __expf(v);   // logits are O(1); exp without max shift is safe in fp32
    }
    int pos = atomicAdd(&g_cur[dst], 1);
    g_ssrc[pos] = src;
    *((float4*)g_salpha + pos) = make_float4(a[0], a[1], a[2], a[3]);
}

// ---------------- K4: warp-per-node aggregation (fp16 gather) ----------------
__global__ __launch_bounds__(256) void k_aggr(const float* __restrict__ bias,
                                              float* __restrict__ out) {
    int w = (blockIdx.x * blockDim.x + threadIdx.x) >> 5;
    if (w >= N_NODES) return;
    int lane = threadIdx.x & 31;
    int h = lane >> 3;

    int start = g_off[w];
    int end   = g_off[w + 1];

    float ax = 0.0f, ay = 0.0f, az = 0.0f, aw = 0.0f, den = 0.0f;

    #pragma unroll 4
    for (int e = start; e < end; e++) {
        int src = __ldg(&g_ssrc[e]);
        float ea = __ldg(&g_salpha[(size_t)e * 4 + h]);
        den += ea;
        uint2 u = __ldg((const uint2*)(g_xh16 + (size_t)src * 128) + lane);
        float2 f0 = __half22float2(*(__half2*)&u.x);
        float2 f1 = __half22float2(*(__half2*)&u.y);
        ax += ea * f0.x; ay += ea * f0.y; az += ea * f1.x; aw += ea * f1.y;
    }

    float inv = 1.0f / (den + 1e-16f);
    float4 b = __ldg((const float4*)bias + lane);
    ((float4*)out)[(size_t)w * 32 + lane] =
        make_float4(ax * inv + b.x, ay * inv + b.y, az * inv + b.z, aw * inv + b.w);
}

// ---------------- launch ----------------------------------------------------
extern "C" void kernel_launch(void* const* d_in, const int* in_sizes, int n_in,
                              void* d_out, int out_size) {
    const float* x     = (const float*)d_in[0];
    const int*   ei    = (const int*)  d_in[1];
    const float* eattr = (const float*)d_in[2];
    const float* W     = (const float*)d_in[3];
    const float* We    = (const float*)d_in[4];
    const float* att   = (const float*)d_in[5];
    const float* bias  = (const float*)d_in[6];
    float* out = (float*)d_out;

    k_init     <<<(N_NODES + 255) / 256, 256>>>(We, att);
    k_gemm_hist<<<GEMM_B + HIST_B, 256>>>(x, W, att, ei);
    k_scan     <<<SCAN_B, 256>>>();
    k_edge     <<<(N_EDGES + 255) / 256, 256>>>(ei, eattr);
    k_aggr     <<<((size_t)N_NODES * 32 + 255) / 256, 256>>>(bias, out);
}